// round 14
// baseline (speedup 1.0000x reference)
#include <cuda_runtime.h>
#include <cuda_fp16.h>
#include <cstdint>

#define NB 8
#define NC 64
#define NPTS 16384
#define NJ 128
#define NCH 32
#define FWD_CHUNK 512
#define FWD_TN 64
#define FWD_TILES 8
#define NCHI 64
#define INV_CHUNK 256
#define INV_TN 64
#define INV_TILES 4

#define FWD_BS 136  // fwd basis row stride elems ([n][j] layout), 272 B
#define FWD_XS 72   // fwd x row stride elems ([c][n]), 144 B
#define INV_S 136   // inv row stride elems, 272 B

// fwd smem per buffer: basis [64 n][136] f16 = 17408 ; x [64 c][72] f16 = 9216
#define F_A   0
#define F_B   17408
#define F_BUF 26624
#define F_TOT (2 * F_BUF)       // 53248
// inv smem: MY f16 static + basis double buffer (TN=64)
#define I_A   0
#define I_B   17408
#define I_BUF 17408
#define I_TOT (I_B + 2 * I_BUF) // 52224

// scratch layout: g_FTp[b][j][ch][c] -- contiguous [ch][c] slab per (b,j)
__device__ float g_FTp[(size_t)NB * NJ * NCH * NC]; // 8 MB
__device__ float g_MY[(size_t)NB * NJ * NC];        // 256 KB

extern __shared__ __align__(16) char dsm[];

// ---------------------------------------------------------------------------
// helpers
// ---------------------------------------------------------------------------
__device__ __forceinline__ uint32_t smem_u32(const void* p) {
    uint32_t a;
    asm("{ .reg .u64 t; cvta.to.shared.u64 t, %1; cvt.u32.u64 %0, t; }" : "=r"(a) : "l"(p));
    return a;
}
__device__ __forceinline__ void ldsm4(uint32_t* r, uint32_t addr) {
    asm volatile("ldmatrix.sync.aligned.m8n8.x4.shared.b16 {%0,%1,%2,%3}, [%4];"
                 : "=r"(r[0]), "=r"(r[1]), "=r"(r[2]), "=r"(r[3]) : "r"(addr));
}
__device__ __forceinline__ void ldsm4t(uint32_t* r, uint32_t addr) {
    asm volatile("ldmatrix.sync.aligned.m8n8.x4.trans.shared.b16 {%0,%1,%2,%3}, [%4];"
                 : "=r"(r[0]), "=r"(r[1]), "=r"(r[2]), "=r"(r[3]) : "r"(addr));
}
__device__ __forceinline__ void mma_f16(float* d, const uint32_t* a, uint32_t b0, uint32_t b1) {
    asm volatile("mma.sync.aligned.m16n8k16.row.col.f32.f16.f16.f32 "
                 "{%0,%1,%2,%3}, {%4,%5,%6,%7}, {%8,%9}, {%0,%1,%2,%3};"
                 : "+f"(d[0]), "+f"(d[1]), "+f"(d[2]), "+f"(d[3])
                 : "r"(a[0]), "r"(a[1]), "r"(a[2]), "r"(a[3]), "r"(b0), "r"(b1));
}
__device__ __forceinline__ uint32_t pk2f(float lo, float hi) {
    __half2 h = __floats2half2_rn(lo, hi);
    return *reinterpret_cast<uint32_t*>(&h);
}

// cos(2*pi*t), sin(2*pi*t) for t in [-0.5, 0.5]; pure FMA pipe. |err| ~ 1e-6.
__device__ __forceinline__ void sincos2pi(float t, float& c, float& s) {
    float t2 = t * t;
    float sp = fmaf(t2, -0.00737046f, 0.08214589f);
    sp = fmaf(t2, sp, -0.59926453f);
    sp = fmaf(t2, sp, 2.55016404f);
    sp = fmaf(t2, sp, -5.16771278f);
    sp = fmaf(t2, sp, 3.14159265f);
    float s1 = t * sp;
    float cp = fmaf(t2, 0.00192958f, -0.02580690f);
    cp = fmaf(t2, cp, 0.23533062f);
    cp = fmaf(t2, cp, -1.33526277f);
    cp = fmaf(t2, cp, 4.05871213f);
    cp = fmaf(t2, cp, -4.93480220f);
    float c1 = fmaf(t2, cp, 1.0f);
    s = 2.0f * s1 * c1;
    c = fmaf(-2.0f * s1, s1, 1.0f);
}

// run 16-step complex recurrence, pack into 8+8 half2 words
__device__ __forceinline__ void chain16(float cr, float ci, float c1r, float c1i,
                                        uint32_t* chb, uint32_t* shb) {
#pragma unroll
    for (int kp = 0; kp < 8; ++kp) {
        float cr0 = cr, ci0 = ci;
        float nr = fmaf(cr, c1r, -ci * c1i);
        float ni_ = fmaf(cr, c1i, ci * c1r);
        cr = nr; ci = ni_;
        chb[kp] = pk2f(cr0, cr);
        shb[kp] = pk2f(ci0, ci);
        nr = fmaf(cr, c1r, -ci * c1i);
        ni_ = fmaf(cr, c1i, ci * c1r);
        cr = nr; ci = ni_;
    }
}

// seed the chain for (p, ckh) and emit 16 packed steps to Bp (basis row layout)
__device__ __forceinline__ void stage_chain(float p, int ckh, char* Bp) {
    float c1r, c1i, cr, ci;
    {
        float f = p - rintf(p);
        sincos2pi(f, c1r, c1i);
    }
    if (ckh == 0) { cr = 1.f; ci = 0.f; }
    else {
        float f = 16.f * p;
        f -= rintf(f);
        sincos2pi(f, cr, ci);
    }
    uint32_t chb[8], shb[8];
    chain16(cr, ci, c1r, c1i, chb, shb);
    *reinterpret_cast<uint4*>(Bp)           = *reinterpret_cast<uint4*>(&chb[0]);
    *reinterpret_cast<uint4*>(Bp + 16)      = *reinterpret_cast<uint4*>(&chb[4]);
    *reinterpret_cast<uint4*>(Bp + 64)      = *reinterpret_cast<uint4*>(&shb[0]);
    *reinterpret_cast<uint4*>(Bp + 64 + 16) = *reinterpret_cast<uint4*>(&shb[4]);
}

// ---------------------------------------------------------------------------
// fwd MMA for one staged tile: 32j x 32c warp tile, K = 64 n (4 ksteps).
// ---------------------------------------------------------------------------
__device__ __forceinline__ void fwd_mma_tile(float acc[2][4][4], uint32_t Aa, uint32_t Ba,
                                             int j0) {
#pragma unroll
    for (int ks = 0; ks < 4; ++ks) {
        uint32_t a[2][4], bh[2][4];
#pragma unroll
        for (int mi = 0; mi < 2; ++mi)
            ldsm4t(a[mi], Aa + (uint32_t)(ks * (16 * 2 * FWD_BS) + (j0 + 16 * mi) * 2));
#pragma unroll
        for (int g = 0; g < 2; ++g)
            ldsm4(bh[g], Ba + (uint32_t)(ks * 32 + g * (16 * 2 * FWD_XS)));
#pragma unroll
        for (int mi = 0; mi < 2; ++mi)
#pragma unroll
            for (int ni = 0; ni < 4; ++ni)
                mma_f16(acc[mi][ni], a[mi], bh[ni >> 1][ni & 1], bh[ni >> 1][(ni & 1) + 2]);
    }
}

// ---------------------------------------------------------------------------
// Forward: g_FTp[b][j=128][ch][c=64] = sum_n Bas[j][n] * x[c][n] (512-chunk)
// ---------------------------------------------------------------------------
__global__ __launch_bounds__(256, 2) void fwd_kernel(const float* __restrict__ x,
                                                     const float* __restrict__ x_in) {
    const int b = blockIdx.y, ch = blockIdx.x;
    const int tid = threadIdx.x, wid = tid >> 5, lane = tid & 31;

    const int j0 = (wid & 3) * 32;
    const int c0 = (wid >> 2) * 32;

    const uint32_t base = smem_u32(dsm);
    const uint32_t n_off = (uint32_t)((lane & 7) + ((lane >> 4) & 1) * 8);
    const uint32_t jl_off = (uint32_t)(((lane >> 3) & 1) * 8);
    const uint32_t Aa = base + F_A + n_off * (2 * FWD_BS) + jl_off * 2;
    const uint32_t b_row = (uint32_t)(c0 + (lane & 7) + ((lane >> 3) & 1) * 8);
    const uint32_t b_col = (uint32_t)((lane >> 4) * 8);
    const uint32_t Ba = base + F_B + (b_row * FWD_XS + b_col) * 2;

    // staging params
    const int cc = tid >> 2;
    const int nq = (tid & 3) * 16;
    const float* xr = x + ((size_t)b * NC + cc) * NPTS;

    const int cn  = tid & 63;
    const int cbr = (tid >> 6) & 1;
    const int ckh = tid >> 7;
    const uint32_t rowb = (uint32_t)(cn * (2 * FWD_BS) + cbr * 128 + ckh * 32);

    float acc[2][4][4];
#pragma unroll
    for (int mi = 0; mi < 2; ++mi)
#pragma unroll
        for (int ni = 0; ni < 4; ++ni)
#pragma unroll
            for (int q = 0; q < 4; ++q) acc[mi][ni][q] = 0.f;

    // preload tile 0 inputs
    float4 xv[4];
    float pv;
    {
        const int n0 = ch * FWD_CHUNK;
#pragma unroll
        for (int g = 0; g < 4; ++g)
            xv[g] = *reinterpret_cast<const float4*>(xr + n0 + nq + 4 * g);
        pv = x_in[((size_t)b * NPTS + n0 + cn) * 2 + cbr];
    }

    for (int t = 0; t < FWD_TILES; ++t) {
        const uint32_t woff = (uint32_t)(t & 1) * F_BUF;
        __half* BS = (__half*)(dsm + woff + F_B);

        __syncthreads();

        // ---- stage x tile from prefetched registers ----
#pragma unroll
        for (int g = 0; g < 4; ++g) {
            int col = nq + 4 * g;
            uint2 v;
            v.x = pk2f(xv[g].x, xv[g].y);
            v.y = pk2f(xv[g].z, xv[g].w);
            *reinterpret_cast<uint2*>(&BS[cc * FWD_XS + col]) = v;
        }

        float pcur = pv;

        // ---- prefetch next tile inputs ----
        if (t + 1 < FWD_TILES) {
            const int n1 = ch * FWD_CHUNK + (t + 1) * FWD_TN;
#pragma unroll
            for (int g = 0; g < 4; ++g)
                xv[g] = *reinterpret_cast<const float4*>(xr + n1 + nq + 4 * g);
            pv = x_in[((size_t)b * NPTS + n1 + cn) * 2 + cbr];
        }

        // ---- MMA tile t-1 (other buffer) ----
        if (t > 0) {
            const uint32_t roff = (uint32_t)((t - 1) & 1) * F_BUF;
            fwd_mma_tile(acc, Aa + roff, Ba + roff, j0);
        }

        // ---- basis chain -> uint4 STS ----
        stage_chain(pcur, ckh, dsm + woff + F_A + rowb);
    }
    // drain last tile
    __syncthreads();
    {
        const uint32_t roff = (uint32_t)((FWD_TILES - 1) & 1) * F_BUF;
        fwd_mma_tile(acc, Aa + roff, Ba + roff, j0);
    }

    // epilogue: D[j][c] -> g_FTp[b][j][ch][c]
#pragma unroll
    for (int mi = 0; mi < 2; ++mi)
#pragma unroll
        for (int ni = 0; ni < 4; ++ni) {
            int jrow = j0 + 16 * mi + (lane >> 2);
            int ccol = c0 + 8 * ni + 2 * (lane & 3);
            float2 v0 = make_float2(acc[mi][ni][0], acc[mi][ni][1]);
            float2 v1 = make_float2(acc[mi][ni][2], acc[mi][ni][3]);
            *reinterpret_cast<float2*>(
                &g_FTp[(((size_t)b * NJ + jrow) * NCH + ch) * NC + ccol]) = v0;
            *reinterpret_cast<float2*>(
                &g_FTp[(((size_t)b * NJ + jrow + 8) * NCH + ch) * NC + ccol]) = v1;
        }
}

// ---------------------------------------------------------------------------
// Mix: reduce chunk partials (contiguous [ch][c] slabs), apply complex weights.
// ---------------------------------------------------------------------------
__global__ __launch_bounds__(256) void mix_kernel(const float* __restrict__ w1,
                                                  const float* __restrict__ w2) {
    const int k = blockIdx.x;
    const int b = blockIdx.y;
    const int tid = threadIdx.x;

    __shared__ float Ared[4][NC];   // rows: br*2 + cs

    {
        int rr = tid >> 6;   // 0..3
        int i  = tid & 63;
        int br = rr >> 1, cs = rr & 1;
        int j = br * 64 + cs * 32 + k;
        const float* basep = g_FTp + ((size_t)b * NJ + j) * NCH * NC + i;
        float s = 0.f;
#pragma unroll 8
        for (int c2 = 0; c2 < NCH; ++c2) s += basep[c2 * NC];
        Ared[rr][i] = s;
    }
    __syncthreads();

    if (tid < 128) {
        const int br = tid >> 6;
        const int o = tid & 63;
        const float* W = (br == 0) ? w1 : w2;
        const float* Ac = Ared[br * 2 + 0];
        const float* As = Ared[br * 2 + 1];
        float mr = 0.f, mi = 0.f;
#pragma unroll 8
        for (int i = 0; i < NC; ++i) {
            float2 w = *reinterpret_cast<const float2*>(W + (((size_t)i * 64 + o) * 32 + k) * 2);
            float ac = Ac[i], as = As[i];
            mr = fmaf(ac, w.x, mr);
            mr = fmaf(as, w.y, mr);
            mi = fmaf(ac, w.y, mi);
            mi = fmaf(-as, w.x, mi);
        }
        g_MY[((size_t)b * NJ + br * 64 + k) * NC + o]      = mr;
        g_MY[((size_t)b * NJ + br * 64 + 32 + k) * NC + o] = -mi;
    }
}

// ---------------------------------------------------------------------------
// Inverse: out[b][o][n] = 64 * sum_j MY[j][o] * Bas_out[j][n]
// TN=64 tiles; 16o x 32n warp tiles; A = MY f16 static, B double-buffered.
// ---------------------------------------------------------------------------
__global__ __launch_bounds__(256, 3) void inv_kernel(const float* __restrict__ x_out,
                                                     float* __restrict__ out) {
    const int b = blockIdx.y, ch = blockIdx.x;
    const int tid = threadIdx.x, wid = tid >> 5, lane = tid & 31;

    __half* AS = (__half*)(dsm + I_A);

    // stage MY once: [o rows][j cols], pairwise packed STS.32
    for (int v = tid; v < NJ * NC / 2; v += 256) {
        int o = v & 63;
        int j2 = v >> 6;  // 0..63
        float a = g_MY[((size_t)b * NJ + 2 * j2) * NC + o];
        float c = g_MY[((size_t)b * NJ + 2 * j2 + 1) * NC + o];
        *reinterpret_cast<uint32_t*>(&AS[o * INV_S + 2 * j2]) = pk2f(a, c);
    }

    const int o0 = (wid & 3) * 16;
    const int nh = (wid >> 2) * 32;

    const uint32_t base = smem_u32(dsm);
    const uint32_t f_row = (uint32_t)((lane & 7) + ((lane >> 3) & 1) * 8);
    const uint32_t kcol = (uint32_t)((lane >> 4) * 8);
    const uint32_t Aa = base + I_A + ((o0 + f_row) * INV_S + kcol) * 2;
    const uint32_t Ba = base + I_B + (f_row * INV_S + kcol) * 2;

    // chain: 1 per thread
    const int cn  = tid & 63;
    const int cbr = (tid >> 6) & 1;
    const int ckh = tid >> 7;
    const uint32_t rowb = (uint32_t)(cn * (INV_S * 2) + cbr * 128 + ckh * 32);

    // preload tile-0 coord
    float p_pre = x_out[((size_t)b * NPTS + ch * INV_CHUNK + cn) * 2 + cbr];

    float acc[4][4];

    for (int t = 0; t < INV_TILES + 1; ++t) {
        __syncthreads();
        // ---- stage basis tile t into buf t&1 ----
        if (t < INV_TILES) {
            char* Bbuf = dsm + I_B + (uint32_t)(t & 1) * I_BUF;
            float pc = p_pre;
            if (t + 1 < INV_TILES) {
                const int n1 = ch * INV_CHUNK + (t + 1) * INV_TN;
                p_pre = x_out[((size_t)b * NPTS + n1 + cn) * 2 + cbr];
            }
            stage_chain(pc, ckh, Bbuf + rowb);
        }
        // ---- MMA tile t-1 from buf (t-1)&1, then store ----
        if (t > 0) {
            const int n0 = ch * INV_CHUNK + (t - 1) * INV_TN;
            const uint32_t roff = (uint32_t)((t - 1) & 1) * I_BUF;
#pragma unroll
            for (int ni = 0; ni < 4; ++ni)
#pragma unroll
                for (int q = 0; q < 4; ++q) acc[ni][q] = 0.f;
#pragma unroll
            for (int ks = 0; ks < 8; ++ks) {
                const uint32_t co = (uint32_t)(ks * 32);
                uint32_t ah[4], bh[2][4];
                ldsm4(ah, Aa + co);
#pragma unroll
                for (int g = 0; g < 2; ++g)
                    ldsm4(bh[g], Ba + roff + (uint32_t)((nh + 16 * g) * (2 * INV_S)) + co);
#pragma unroll
                for (int ni = 0; ni < 4; ++ni)
                    mma_f16(acc[ni], ah, bh[ni >> 1][ni & 1], bh[ni >> 1][(ni & 1) + 2]);
            }
#pragma unroll
            for (int ni = 0; ni < 4; ++ni) {
                int orow = o0 + (lane >> 2);
                int n = n0 + nh + 8 * ni + 2 * (lane & 3);
                float2 v0 = make_float2(64.f * acc[ni][0], 64.f * acc[ni][1]);
                float2 v1 = make_float2(64.f * acc[ni][2], 64.f * acc[ni][3]);
                *reinterpret_cast<float2*>(&out[((size_t)(b * NC + orow)) * NPTS + n])     = v0;
                *reinterpret_cast<float2*>(&out[((size_t)(b * NC + orow + 8)) * NPTS + n]) = v1;
            }
        }
    }
}

// ---------------------------------------------------------------------------
extern "C" void kernel_launch(void* const* d_in, const int* in_sizes, int n_in,
                              void* d_out, int out_size) {
    const float* x     = (const float*)d_in[0];
    const float* x_in  = (const float*)d_in[1];
    const float* x_out = (const float*)d_in[2];
    const float* w1    = (const float*)d_in[3];
    const float* w2    = (const float*)d_in[4];
    float* out = (float*)d_out;

    cudaFuncSetAttribute(fwd_kernel, cudaFuncAttributeMaxDynamicSharedMemorySize, F_TOT);
    cudaFuncSetAttribute(inv_kernel, cudaFuncAttributeMaxDynamicSharedMemorySize, I_TOT);

    fwd_kernel<<<dim3(NCH, NB), 256, F_TOT>>>(x, x_in);
    mix_kernel<<<dim3(32, NB), 256>>>(w1, w2);
    inv_kernel<<<dim3(NCHI, NB), 256, I_TOT>>>(x_out, out);
}

// round 15
// speedup vs baseline: 1.0642x; 1.0642x over previous
#include <cuda_runtime.h>
#include <cuda_fp16.h>
#include <cstdint>

#define NB 8
#define NC 64
#define NPTS 16384
#define NJ 128
#define NCH 32
#define FWD_CHUNK 512
#define FWD_TN 64
#define FWD_TILES 8
#define NCHI 32
#define INV_CHUNK 512
#define INV_TN 128
#define INV_TILES 4

#define FWD_BS 136  // fwd basis row stride elems ([n][j] layout), 272 B
#define FWD_XS 72   // fwd x row stride elems ([c][n]), 144 B
#define INV_S 136   // inv row stride elems, 272 B

// fwd smem per buffer: basis [64 n][136] f16 = 17408 ; x [64 c][72] f16 = 9216
#define F_A   0
#define F_B   17408
#define F_BUF 26624
#define F_TOT (2 * F_BUF)       // 53248
// inv smem: MY f16 static + basis double buffer (TN=128)
#define I_A   0
#define I_B   17408
#define I_BUF 34816
#define I_TOT (I_B + 2 * I_BUF) // 87040

// scratch layout: g_FTp[b][j][ch][c] -- contiguous [ch][c] slab per (b,j)
__device__ float g_FTp[(size_t)NB * NJ * NCH * NC]; // 8 MB
__device__ float g_MY[(size_t)NB * NJ * NC];        // 256 KB

extern __shared__ __align__(16) char dsm[];

// ---------------------------------------------------------------------------
// helpers
// ---------------------------------------------------------------------------
__device__ __forceinline__ uint32_t smem_u32(const void* p) {
    uint32_t a;
    asm("{ .reg .u64 t; cvta.to.shared.u64 t, %1; cvt.u32.u64 %0, t; }" : "=r"(a) : "l"(p));
    return a;
}
__device__ __forceinline__ void ldsm4(uint32_t* r, uint32_t addr) {
    asm volatile("ldmatrix.sync.aligned.m8n8.x4.shared.b16 {%0,%1,%2,%3}, [%4];"
                 : "=r"(r[0]), "=r"(r[1]), "=r"(r[2]), "=r"(r[3]) : "r"(addr));
}
__device__ __forceinline__ void ldsm4t(uint32_t* r, uint32_t addr) {
    asm volatile("ldmatrix.sync.aligned.m8n8.x4.trans.shared.b16 {%0,%1,%2,%3}, [%4];"
                 : "=r"(r[0]), "=r"(r[1]), "=r"(r[2]), "=r"(r[3]) : "r"(addr));
}
__device__ __forceinline__ void mma_f16(float* d, const uint32_t* a, uint32_t b0, uint32_t b1) {
    asm volatile("mma.sync.aligned.m16n8k16.row.col.f32.f16.f16.f32 "
                 "{%0,%1,%2,%3}, {%4,%5,%6,%7}, {%8,%9}, {%0,%1,%2,%3};"
                 : "+f"(d[0]), "+f"(d[1]), "+f"(d[2]), "+f"(d[3])
                 : "r"(a[0]), "r"(a[1]), "r"(a[2]), "r"(a[3]), "r"(b0), "r"(b1));
}
__device__ __forceinline__ uint32_t pk2f(float lo, float hi) {
    __half2 h = __floats2half2_rn(lo, hi);
    return *reinterpret_cast<uint32_t*>(&h);
}

// cos(2*pi*t), sin(2*pi*t) for t in [-0.5, 0.5]; pure FMA pipe. |err| ~ 1e-6.
__device__ __forceinline__ void sincos2pi(float t, float& c, float& s) {
    float t2 = t * t;
    float sp = fmaf(t2, -0.00737046f, 0.08214589f);
    sp = fmaf(t2, sp, -0.59926453f);
    sp = fmaf(t2, sp, 2.55016404f);
    sp = fmaf(t2, sp, -5.16771278f);
    sp = fmaf(t2, sp, 3.14159265f);
    float s1 = t * sp;
    float cp = fmaf(t2, 0.00192958f, -0.02580690f);
    cp = fmaf(t2, cp, 0.23533062f);
    cp = fmaf(t2, cp, -1.33526277f);
    cp = fmaf(t2, cp, 4.05871213f);
    cp = fmaf(t2, cp, -4.93480220f);
    float c1 = fmaf(t2, cp, 1.0f);
    s = 2.0f * s1 * c1;
    c = fmaf(-2.0f * s1, s1, 1.0f);
}

// run 16-step complex recurrence, pack into 8+8 half2 words
__device__ __forceinline__ void chain16(float cr, float ci, float c1r, float c1i,
                                        uint32_t* chb, uint32_t* shb) {
#pragma unroll
    for (int kp = 0; kp < 8; ++kp) {
        float cr0 = cr, ci0 = ci;
        float nr = fmaf(cr, c1r, -ci * c1i);
        float ni_ = fmaf(cr, c1i, ci * c1r);
        cr = nr; ci = ni_;
        chb[kp] = pk2f(cr0, cr);
        shb[kp] = pk2f(ci0, ci);
        nr = fmaf(cr, c1r, -ci * c1i);
        ni_ = fmaf(cr, c1i, ci * c1r);
        cr = nr; ci = ni_;
    }
}

// seed the chain for (p, ckh) and emit 16 packed steps to Bp (basis row layout)
__device__ __forceinline__ void stage_chain(float p, int ckh, char* Bp) {
    float c1r, c1i, cr, ci;
    {
        float f = p - rintf(p);
        sincos2pi(f, c1r, c1i);
    }
    if (ckh == 0) { cr = 1.f; ci = 0.f; }
    else {
        float f = 16.f * p;
        f -= rintf(f);
        sincos2pi(f, cr, ci);
    }
    uint32_t chb[8], shb[8];
    chain16(cr, ci, c1r, c1i, chb, shb);
    *reinterpret_cast<uint4*>(Bp)           = *reinterpret_cast<uint4*>(&chb[0]);
    *reinterpret_cast<uint4*>(Bp + 16)      = *reinterpret_cast<uint4*>(&chb[4]);
    *reinterpret_cast<uint4*>(Bp + 64)      = *reinterpret_cast<uint4*>(&shb[0]);
    *reinterpret_cast<uint4*>(Bp + 64 + 16) = *reinterpret_cast<uint4*>(&shb[4]);
}

// ---------------------------------------------------------------------------
// fwd MMA for one staged tile: 32j x 32c warp tile, K = 64 n (4 ksteps).
// ---------------------------------------------------------------------------
__device__ __forceinline__ void fwd_mma_tile(float acc[2][4][4], uint32_t Aa, uint32_t Ba,
                                             int j0) {
#pragma unroll
    for (int ks = 0; ks < 4; ++ks) {
        uint32_t a[2][4], bh[2][4];
#pragma unroll
        for (int mi = 0; mi < 2; ++mi)
            ldsm4t(a[mi], Aa + (uint32_t)(ks * (16 * 2 * FWD_BS) + (j0 + 16 * mi) * 2));
#pragma unroll
        for (int g = 0; g < 2; ++g)
            ldsm4(bh[g], Ba + (uint32_t)(ks * 32 + g * (16 * 2 * FWD_XS)));
#pragma unroll
        for (int mi = 0; mi < 2; ++mi)
#pragma unroll
            for (int ni = 0; ni < 4; ++ni)
                mma_f16(acc[mi][ni], a[mi], bh[ni >> 1][ni & 1], bh[ni >> 1][(ni & 1) + 2]);
    }
}

// ---------------------------------------------------------------------------
// Forward: g_FTp[b][j=128][ch][c=64] = sum_n Bas[j][n] * x[c][n] (512-chunk)
// ---------------------------------------------------------------------------
__global__ __launch_bounds__(256, 2) void fwd_kernel(const float* __restrict__ x,
                                                     const float* __restrict__ x_in) {
    const int b = blockIdx.y, ch = blockIdx.x;
    const int tid = threadIdx.x, wid = tid >> 5, lane = tid & 31;

    const int j0 = (wid & 3) * 32;
    const int c0 = (wid >> 2) * 32;

    const uint32_t base = smem_u32(dsm);
    const uint32_t n_off = (uint32_t)((lane & 7) + ((lane >> 4) & 1) * 8);
    const uint32_t jl_off = (uint32_t)(((lane >> 3) & 1) * 8);
    const uint32_t Aa = base + F_A + n_off * (2 * FWD_BS) + jl_off * 2;
    const uint32_t b_row = (uint32_t)(c0 + (lane & 7) + ((lane >> 3) & 1) * 8);
    const uint32_t b_col = (uint32_t)((lane >> 4) * 8);
    const uint32_t Ba = base + F_B + (b_row * FWD_XS + b_col) * 2;

    // staging params
    const int cc = tid >> 2;
    const int nq = (tid & 3) * 16;
    const float* xr = x + ((size_t)b * NC + cc) * NPTS;

    const int cn  = tid & 63;
    const int cbr = (tid >> 6) & 1;
    const int ckh = tid >> 7;
    const uint32_t rowb = (uint32_t)(cn * (2 * FWD_BS) + cbr * 128 + ckh * 32);

    float acc[2][4][4];
#pragma unroll
    for (int mi = 0; mi < 2; ++mi)
#pragma unroll
        for (int ni = 0; ni < 4; ++ni)
#pragma unroll
            for (int q = 0; q < 4; ++q) acc[mi][ni][q] = 0.f;

    // preload tile 0 inputs
    float4 xv[4];
    float pv;
    {
        const int n0 = ch * FWD_CHUNK;
#pragma unroll
        for (int g = 0; g < 4; ++g)
            xv[g] = *reinterpret_cast<const float4*>(xr + n0 + nq + 4 * g);
        pv = x_in[((size_t)b * NPTS + n0 + cn) * 2 + cbr];
    }

    for (int t = 0; t < FWD_TILES; ++t) {
        const uint32_t woff = (uint32_t)(t & 1) * F_BUF;
        __half* BS = (__half*)(dsm + woff + F_B);

        __syncthreads();

        // ---- stage x tile from prefetched registers ----
#pragma unroll
        for (int g = 0; g < 4; ++g) {
            int col = nq + 4 * g;
            uint2 v;
            v.x = pk2f(xv[g].x, xv[g].y);
            v.y = pk2f(xv[g].z, xv[g].w);
            *reinterpret_cast<uint2*>(&BS[cc * FWD_XS + col]) = v;
        }

        float pcur = pv;

        // ---- prefetch next tile inputs ----
        if (t + 1 < FWD_TILES) {
            const int n1 = ch * FWD_CHUNK + (t + 1) * FWD_TN;
#pragma unroll
            for (int g = 0; g < 4; ++g)
                xv[g] = *reinterpret_cast<const float4*>(xr + n1 + nq + 4 * g);
            pv = x_in[((size_t)b * NPTS + n1 + cn) * 2 + cbr];
        }

        // ---- MMA tile t-1 (other buffer) ----
        if (t > 0) {
            const uint32_t roff = (uint32_t)((t - 1) & 1) * F_BUF;
            fwd_mma_tile(acc, Aa + roff, Ba + roff, j0);
        }

        // ---- basis chain -> uint4 STS ----
        stage_chain(pcur, ckh, dsm + woff + F_A + rowb);
    }
    // drain last tile
    __syncthreads();
    {
        const uint32_t roff = (uint32_t)((FWD_TILES - 1) & 1) * F_BUF;
        fwd_mma_tile(acc, Aa + roff, Ba + roff, j0);
    }

    // epilogue: D[j][c] -> g_FTp[b][j][ch][c]
#pragma unroll
    for (int mi = 0; mi < 2; ++mi)
#pragma unroll
        for (int ni = 0; ni < 4; ++ni) {
            int jrow = j0 + 16 * mi + (lane >> 2);
            int ccol = c0 + 8 * ni + 2 * (lane & 3);
            float2 v0 = make_float2(acc[mi][ni][0], acc[mi][ni][1]);
            float2 v1 = make_float2(acc[mi][ni][2], acc[mi][ni][3]);
            *reinterpret_cast<float2*>(
                &g_FTp[(((size_t)b * NJ + jrow) * NCH + ch) * NC + ccol]) = v0;
            *reinterpret_cast<float2*>(
                &g_FTp[(((size_t)b * NJ + jrow + 8) * NCH + ch) * NC + ccol]) = v1;
        }
}

// ---------------------------------------------------------------------------
// Mix: reduce chunk partials (contiguous [ch][c] slabs), apply complex weights.
// ---------------------------------------------------------------------------
__global__ __launch_bounds__(256) void mix_kernel(const float* __restrict__ w1,
                                                  const float* __restrict__ w2) {
    const int k = blockIdx.x;
    const int b = blockIdx.y;
    const int tid = threadIdx.x;

    __shared__ float Ared[4][NC];   // rows: br*2 + cs

    {
        int rr = tid >> 6;   // 0..3
        int i  = tid & 63;
        int br = rr >> 1, cs = rr & 1;
        int j = br * 64 + cs * 32 + k;
        const float* basep = g_FTp + ((size_t)b * NJ + j) * NCH * NC + i;
        float s = 0.f;
#pragma unroll 8
        for (int c2 = 0; c2 < NCH; ++c2) s += basep[c2 * NC];
        Ared[rr][i] = s;
    }
    __syncthreads();

    if (tid < 128) {
        const int br = tid >> 6;
        const int o = tid & 63;
        const float* W = (br == 0) ? w1 : w2;
        const float* Ac = Ared[br * 2 + 0];
        const float* As = Ared[br * 2 + 1];
        float mr = 0.f, mi = 0.f;
#pragma unroll 8
        for (int i = 0; i < NC; ++i) {
            float2 w = *reinterpret_cast<const float2*>(W + (((size_t)i * 64 + o) * 32 + k) * 2);
            float ac = Ac[i], as = As[i];
            mr = fmaf(ac, w.x, mr);
            mr = fmaf(as, w.y, mr);
            mi = fmaf(ac, w.y, mi);
            mi = fmaf(-as, w.x, mi);
        }
        g_MY[((size_t)b * NJ + br * 64 + k) * NC + o]      = mr;
        g_MY[((size_t)b * NJ + br * 64 + 32 + k) * NC + o] = -mi;
    }
}

// ---------------------------------------------------------------------------
// Inverse: out[b][o][n] = 64 * sum_j MY[j][o] * Bas_out[j][n]
// R11 structure: TN=128, 32o x 32n warp tiles, inline 2-chain staging,
// no coordinate prefetch. A = MY f16 static, B = basis double-buffered.
// ---------------------------------------------------------------------------
__global__ __launch_bounds__(256, 2) void inv_kernel(const float* __restrict__ x_out,
                                                     float* __restrict__ out) {
    const int b = blockIdx.y, ch = blockIdx.x;
    const int tid = threadIdx.x, wid = tid >> 5, lane = tid & 31;

    __half* AS = (__half*)(dsm + I_A);

    // stage MY once: [o rows][j cols], single f16 (scalar, R11-style)
    for (int v = tid; v < NJ * NC; v += 256) {
        int o = v & 63;
        int j = v >> 6;
        AS[o * INV_S + j] = __float2half_rn(g_MY[((size_t)b * NJ + j) * NC + o]);
    }

    const int o0 = (wid & 1) * 32;
    const int nh = (wid >> 1) * 32;

    const uint32_t base = smem_u32(dsm);
    const uint32_t f_row = (uint32_t)((lane & 7) + ((lane >> 3) & 1) * 8);
    const uint32_t kcol = (uint32_t)((lane >> 4) * 8);
    const uint32_t Aa = base + I_A + (f_row * INV_S + kcol) * 2;
    const uint32_t Ba = base + I_B + (f_row * INV_S + kcol) * 2;

    float acc[2][4][4];

    for (int t = 0; t < INV_TILES + 1; ++t) {
        __syncthreads();
        // ---- stage basis tile t into buf t&1 (inline 2 chains/thread) ----
        if (t < INV_TILES) {
            const int n0 = ch * INV_CHUNK + t * INV_TN;
            char* Bbuf = dsm + I_B + (uint32_t)(t & 1) * I_BUF;
#pragma unroll
            for (int r = 0; r < 2; ++r) {
                int id  = tid + r * 256;
                int n   = id & 127;
                int cbr = (id >> 7) & 1;
                int ckh = id >> 8;
                float p = x_out[((size_t)b * NPTS + n0 + n) * 2 + cbr];
                uint32_t rowb = (uint32_t)(n * (INV_S * 2) + cbr * 128 + ckh * 32);
                stage_chain(p, ckh, Bbuf + rowb);
            }
        }
        // ---- MMA tile t-1 from buf (t-1)&1, then store ----
        if (t > 0) {
            const int n0 = ch * INV_CHUNK + (t - 1) * INV_TN;
            const uint32_t roff = (uint32_t)((t - 1) & 1) * I_BUF;
#pragma unroll
            for (int mi = 0; mi < 2; ++mi)
#pragma unroll
                for (int ni = 0; ni < 4; ++ni)
#pragma unroll
                    for (int q = 0; q < 4; ++q) acc[mi][ni][q] = 0.f;
#pragma unroll
            for (int ks = 0; ks < 8; ++ks) {
                const uint32_t co = (uint32_t)(ks * 32);
                uint32_t ah[2][4], bh[2][4];
#pragma unroll
                for (int mi = 0; mi < 2; ++mi)
                    ldsm4(ah[mi], Aa + (uint32_t)((o0 + 16 * mi) * (2 * INV_S)) + co);
#pragma unroll
                for (int g = 0; g < 2; ++g)
                    ldsm4(bh[g], Ba + roff + (uint32_t)((nh + 16 * g) * (2 * INV_S)) + co);
#pragma unroll
                for (int mi = 0; mi < 2; ++mi)
#pragma unroll
                    for (int ni = 0; ni < 4; ++ni)
                        mma_f16(acc[mi][ni], ah[mi], bh[ni >> 1][ni & 1], bh[ni >> 1][(ni & 1) + 2]);
            }
#pragma unroll
            for (int mi = 0; mi < 2; ++mi)
#pragma unroll
                for (int ni = 0; ni < 4; ++ni) {
                    int orow = o0 + 16 * mi + (lane >> 2);
                    int n = n0 + nh + 8 * ni + 2 * (lane & 3);
                    float2 v0 = make_float2(64.f * acc[mi][ni][0], 64.f * acc[mi][ni][1]);
                    float2 v1 = make_float2(64.f * acc[mi][ni][2], 64.f * acc[mi][ni][3]);
                    *reinterpret_cast<float2*>(&out[((size_t)(b * NC + orow)) * NPTS + n])     = v0;
                    *reinterpret_cast<float2*>(&out[((size_t)(b * NC + orow + 8)) * NPTS + n]) = v1;
                }
        }
    }
}

// ---------------------------------------------------------------------------
extern "C" void kernel_launch(void* const* d_in, const int* in_sizes, int n_in,
                              void* d_out, int out_size) {
    const float* x     = (const float*)d_in[0];
    const float* x_in  = (const float*)d_in[1];
    const float* x_out = (const float*)d_in[2];
    const float* w1    = (const float*)d_in[3];
    const float* w2    = (const float*)d_in[4];
    float* out = (float*)d_out;

    cudaFuncSetAttribute(fwd_kernel, cudaFuncAttributeMaxDynamicSharedMemorySize, F_TOT);
    cudaFuncSetAttribute(inv_kernel, cudaFuncAttributeMaxDynamicSharedMemorySize, I_TOT);

    fwd_kernel<<<dim3(NCH, NB), 256, F_TOT>>>(x, x_in);
    mix_kernel<<<dim3(32, NB), 256>>>(w1, w2);
    inv_kernel<<<dim3(NCHI, NB), 256, I_TOT>>>(x_out, out);
}

// round 16
// speedup vs baseline: 1.0649x; 1.0007x over previous
#include <cuda_runtime.h>
#include <cuda_fp16.h>
#include <cstdint>

#define NB 8
#define NC 64
#define NPTS 16384
#define NJ 128
#define NCH 32
#define FWD_CHUNK 512
#define FWD_TN 64
#define FWD_TILES 8
#define NCHI 32
#define INV_CHUNK 512
#define INV_TN 128
#define INV_TILES 4

#define FWD_BS 136  // fwd basis row stride elems ([n][j] layout), 272 B
#define FWD_XS 72   // fwd x row stride elems ([c][n]), 144 B
#define INV_S 136   // inv row stride elems, 272 B

// fwd smem per buffer: basis [64 n][136] f16 = 17408 ; x [64 c][72] f16 = 9216
#define F_A   0
#define F_B   17408
#define F_BUF 26624
#define F_TOT (2 * F_BUF)       // 53248
// inv smem: MY f16 static + basis double buffer (TN=128)
#define I_A   0
#define I_B   17408
#define I_BUF 34816
#define I_TOT (I_B + 2 * I_BUF) // 87040

// scratch layout: g_FTp[b][j][ch][c] -- contiguous [ch][c] slab per (b,j)
__device__ float g_FTp[(size_t)NB * NJ * NCH * NC]; // 8 MB
__device__ float g_MY[(size_t)NB * NJ * NC];        // 256 KB

extern __shared__ __align__(16) char dsm[];

// ---------------------------------------------------------------------------
// helpers
// ---------------------------------------------------------------------------
__device__ __forceinline__ uint32_t smem_u32(const void* p) {
    uint32_t a;
    asm("{ .reg .u64 t; cvta.to.shared.u64 t, %1; cvt.u32.u64 %0, t; }" : "=r"(a) : "l"(p));
    return a;
}
__device__ __forceinline__ void ldsm4(uint32_t* r, uint32_t addr) {
    asm volatile("ldmatrix.sync.aligned.m8n8.x4.shared.b16 {%0,%1,%2,%3}, [%4];"
                 : "=r"(r[0]), "=r"(r[1]), "=r"(r[2]), "=r"(r[3]) : "r"(addr));
}
__device__ __forceinline__ void ldsm4t(uint32_t* r, uint32_t addr) {
    asm volatile("ldmatrix.sync.aligned.m8n8.x4.trans.shared.b16 {%0,%1,%2,%3}, [%4];"
                 : "=r"(r[0]), "=r"(r[1]), "=r"(r[2]), "=r"(r[3]) : "r"(addr));
}
__device__ __forceinline__ void mma_f16(float* d, const uint32_t* a, uint32_t b0, uint32_t b1) {
    asm volatile("mma.sync.aligned.m16n8k16.row.col.f32.f16.f16.f32 "
                 "{%0,%1,%2,%3}, {%4,%5,%6,%7}, {%8,%9}, {%0,%1,%2,%3};"
                 : "+f"(d[0]), "+f"(d[1]), "+f"(d[2]), "+f"(d[3])
                 : "r"(a[0]), "r"(a[1]), "r"(a[2]), "r"(a[3]), "r"(b0), "r"(b1));
}
__device__ __forceinline__ uint32_t pk2f(float lo, float hi) {
    __half2 h = __floats2half2_rn(lo, hi);
    return *reinterpret_cast<uint32_t*>(&h);
}

// cos(2*pi*t), sin(2*pi*t) for t in [-0.5, 0.5]; pure FMA pipe. |err| ~ 1e-6.
__device__ __forceinline__ void sincos2pi(float t, float& c, float& s) {
    float t2 = t * t;
    float sp = fmaf(t2, -0.00737046f, 0.08214589f);
    sp = fmaf(t2, sp, -0.59926453f);
    sp = fmaf(t2, sp, 2.55016404f);
    sp = fmaf(t2, sp, -5.16771278f);
    sp = fmaf(t2, sp, 3.14159265f);
    float s1 = t * sp;
    float cp = fmaf(t2, 0.00192958f, -0.02580690f);
    cp = fmaf(t2, cp, 0.23533062f);
    cp = fmaf(t2, cp, -1.33526277f);
    cp = fmaf(t2, cp, 4.05871213f);
    cp = fmaf(t2, cp, -4.93480220f);
    float c1 = fmaf(t2, cp, 1.0f);
    s = 2.0f * s1 * c1;
    c = fmaf(-2.0f * s1, s1, 1.0f);
}

// run 16-step complex recurrence, pack into 8+8 half2 words
__device__ __forceinline__ void chain16(float cr, float ci, float c1r, float c1i,
                                        uint32_t* chb, uint32_t* shb) {
#pragma unroll
    for (int kp = 0; kp < 8; ++kp) {
        float cr0 = cr, ci0 = ci;
        float nr = fmaf(cr, c1r, -ci * c1i);
        float ni_ = fmaf(cr, c1i, ci * c1r);
        cr = nr; ci = ni_;
        chb[kp] = pk2f(cr0, cr);
        shb[kp] = pk2f(ci0, ci);
        nr = fmaf(cr, c1r, -ci * c1i);
        ni_ = fmaf(cr, c1i, ci * c1r);
        cr = nr; ci = ni_;
    }
}

// seed the chain for (p, ckh) and emit 16 packed steps to Bp (basis row layout)
__device__ __forceinline__ void stage_chain(float p, int ckh, char* Bp) {
    float c1r, c1i, cr, ci;
    {
        float f = p - rintf(p);
        sincos2pi(f, c1r, c1i);
    }
    if (ckh == 0) { cr = 1.f; ci = 0.f; }
    else {
        float f = 16.f * p;
        f -= rintf(f);
        sincos2pi(f, cr, ci);
    }
    uint32_t chb[8], shb[8];
    chain16(cr, ci, c1r, c1i, chb, shb);
    *reinterpret_cast<uint4*>(Bp)           = *reinterpret_cast<uint4*>(&chb[0]);
    *reinterpret_cast<uint4*>(Bp + 16)      = *reinterpret_cast<uint4*>(&chb[4]);
    *reinterpret_cast<uint4*>(Bp + 64)      = *reinterpret_cast<uint4*>(&shb[0]);
    *reinterpret_cast<uint4*>(Bp + 64 + 16) = *reinterpret_cast<uint4*>(&shb[4]);
}

// ---------------------------------------------------------------------------
// fwd MMA for one staged tile: 32j x 32c warp tile, K = 64 n (4 ksteps).
// ---------------------------------------------------------------------------
__device__ __forceinline__ void fwd_mma_tile(float acc[2][4][4], uint32_t Aa, uint32_t Ba,
                                             int j0) {
#pragma unroll
    for (int ks = 0; ks < 4; ++ks) {
        uint32_t a[2][4], bh[2][4];
#pragma unroll
        for (int mi = 0; mi < 2; ++mi)
            ldsm4t(a[mi], Aa + (uint32_t)(ks * (16 * 2 * FWD_BS) + (j0 + 16 * mi) * 2));
#pragma unroll
        for (int g = 0; g < 2; ++g)
            ldsm4(bh[g], Ba + (uint32_t)(ks * 32 + g * (16 * 2 * FWD_XS)));
#pragma unroll
        for (int mi = 0; mi < 2; ++mi)
#pragma unroll
            for (int ni = 0; ni < 4; ++ni)
                mma_f16(acc[mi][ni], a[mi], bh[ni >> 1][ni & 1], bh[ni >> 1][(ni & 1) + 2]);
    }
}

// ---------------------------------------------------------------------------
// Forward: g_FTp[b][j=128][ch][c=64] = sum_n Bas[j][n] * x[c][n] (512-chunk)
// ---------------------------------------------------------------------------
__global__ __launch_bounds__(256, 2) void fwd_kernel(const float* __restrict__ x,
                                                     const float* __restrict__ x_in) {
    const int b = blockIdx.y, ch = blockIdx.x;
    const int tid = threadIdx.x, wid = tid >> 5, lane = tid & 31;

    const int j0 = (wid & 3) * 32;
    const int c0 = (wid >> 2) * 32;

    const uint32_t base = smem_u32(dsm);
    const uint32_t n_off = (uint32_t)((lane & 7) + ((lane >> 4) & 1) * 8);
    const uint32_t jl_off = (uint32_t)(((lane >> 3) & 1) * 8);
    const uint32_t Aa = base + F_A + n_off * (2 * FWD_BS) + jl_off * 2;
    const uint32_t b_row = (uint32_t)(c0 + (lane & 7) + ((lane >> 3) & 1) * 8);
    const uint32_t b_col = (uint32_t)((lane >> 4) * 8);
    const uint32_t Ba = base + F_B + (b_row * FWD_XS + b_col) * 2;

    // staging params
    const int cc = tid >> 2;
    const int nq = (tid & 3) * 16;
    const float* xr = x + ((size_t)b * NC + cc) * NPTS;

    const int cn  = tid & 63;
    const int cbr = (tid >> 6) & 1;
    const int ckh = tid >> 7;
    const uint32_t rowb = (uint32_t)(cn * (2 * FWD_BS) + cbr * 128 + ckh * 32);

    float acc[2][4][4];
#pragma unroll
    for (int mi = 0; mi < 2; ++mi)
#pragma unroll
        for (int ni = 0; ni < 4; ++ni)
#pragma unroll
            for (int q = 0; q < 4; ++q) acc[mi][ni][q] = 0.f;

    // preload tile 0 inputs
    float4 xv[4];
    float pv;
    {
        const int n0 = ch * FWD_CHUNK;
#pragma unroll
        for (int g = 0; g < 4; ++g)
            xv[g] = *reinterpret_cast<const float4*>(xr + n0 + nq + 4 * g);
        pv = x_in[((size_t)b * NPTS + n0 + cn) * 2 + cbr];
    }

    for (int t = 0; t < FWD_TILES; ++t) {
        const uint32_t woff = (uint32_t)(t & 1) * F_BUF;
        __half* BS = (__half*)(dsm + woff + F_B);

        __syncthreads();

        // ---- stage x tile from prefetched registers ----
#pragma unroll
        for (int g = 0; g < 4; ++g) {
            int col = nq + 4 * g;
            uint2 v;
            v.x = pk2f(xv[g].x, xv[g].y);
            v.y = pk2f(xv[g].z, xv[g].w);
            *reinterpret_cast<uint2*>(&BS[cc * FWD_XS + col]) = v;
        }

        float pcur = pv;

        // ---- prefetch next tile inputs ----
        if (t + 1 < FWD_TILES) {
            const int n1 = ch * FWD_CHUNK + (t + 1) * FWD_TN;
#pragma unroll
            for (int g = 0; g < 4; ++g)
                xv[g] = *reinterpret_cast<const float4*>(xr + n1 + nq + 4 * g);
            pv = x_in[((size_t)b * NPTS + n1 + cn) * 2 + cbr];
        }

        // ---- MMA tile t-1 (other buffer) ----
        if (t > 0) {
            const uint32_t roff = (uint32_t)((t - 1) & 1) * F_BUF;
            fwd_mma_tile(acc, Aa + roff, Ba + roff, j0);
        }

        // ---- basis chain -> uint4 STS ----
        stage_chain(pcur, ckh, dsm + woff + F_A + rowb);
    }
    // drain last tile
    __syncthreads();
    {
        const uint32_t roff = (uint32_t)((FWD_TILES - 1) & 1) * F_BUF;
        fwd_mma_tile(acc, Aa + roff, Ba + roff, j0);
    }

    // epilogue: D[j][c] -> g_FTp[b][j][ch][c]
#pragma unroll
    for (int mi = 0; mi < 2; ++mi)
#pragma unroll
        for (int ni = 0; ni < 4; ++ni) {
            int jrow = j0 + 16 * mi + (lane >> 2);
            int ccol = c0 + 8 * ni + 2 * (lane & 3);
            float2 v0 = make_float2(acc[mi][ni][0], acc[mi][ni][1]);
            float2 v1 = make_float2(acc[mi][ni][2], acc[mi][ni][3]);
            *reinterpret_cast<float2*>(
                &g_FTp[(((size_t)b * NJ + jrow) * NCH + ch) * NC + ccol]) = v0;
            *reinterpret_cast<float2*>(
                &g_FTp[(((size_t)b * NJ + jrow + 8) * NCH + ch) * NC + ccol]) = v1;
        }
}

// ---------------------------------------------------------------------------
// Mix: reduce chunk partials (contiguous [ch][c] slabs), apply complex weights.
// ---------------------------------------------------------------------------
__global__ __launch_bounds__(256) void mix_kernel(const float* __restrict__ w1,
                                                  const float* __restrict__ w2) {
    const int k = blockIdx.x;
    const int b = blockIdx.y;
    const int tid = threadIdx.x;

    __shared__ float Ared[4][NC];   // rows: br*2 + cs

    {
        int rr = tid >> 6;   // 0..3
        int i  = tid & 63;
        int br = rr >> 1, cs = rr & 1;
        int j = br * 64 + cs * 32 + k;
        const float* basep = g_FTp + ((size_t)b * NJ + j) * NCH * NC + i;
        float s = 0.f;
#pragma unroll 8
        for (int c2 = 0; c2 < NCH; ++c2) s += basep[c2 * NC];
        Ared[rr][i] = s;
    }
    __syncthreads();

    if (tid < 128) {
        const int br = tid >> 6;
        const int o = tid & 63;
        const float* W = (br == 0) ? w1 : w2;
        const float* Ac = Ared[br * 2 + 0];
        const float* As = Ared[br * 2 + 1];
        float mr = 0.f, mi = 0.f;
#pragma unroll 8
        for (int i = 0; i < NC; ++i) {
            float2 w = *reinterpret_cast<const float2*>(W + (((size_t)i * 64 + o) * 32 + k) * 2);
            float ac = Ac[i], as = As[i];
            mr = fmaf(ac, w.x, mr);
            mr = fmaf(as, w.y, mr);
            mi = fmaf(ac, w.y, mi);
            mi = fmaf(-as, w.x, mi);
        }
        g_MY[((size_t)b * NJ + br * 64 + k) * NC + o]      = mr;
        g_MY[((size_t)b * NJ + br * 64 + 32 + k) * NC + o] = -mi;
    }
}

// ---------------------------------------------------------------------------
// Inverse: out[b][o][n] = 64 * sum_j MY[j][o] * Bas_out[j][n]
// R11 structure + minimal coordinate prefetch (2 scalar regs, inline indices).
// ---------------------------------------------------------------------------
__global__ __launch_bounds__(256, 2) void inv_kernel(const float* __restrict__ x_out,
                                                     float* __restrict__ out) {
    const int b = blockIdx.y, ch = blockIdx.x;
    const int tid = threadIdx.x, wid = tid >> 5, lane = tid & 31;

    __half* AS = (__half*)(dsm + I_A);

    // stage MY once: [o rows][j cols], single f16 (scalar)
    for (int v = tid; v < NJ * NC; v += 256) {
        int o = v & 63;
        int j = v >> 6;
        AS[o * INV_S + j] = __float2half_rn(g_MY[((size_t)b * NJ + j) * NC + o]);
    }

    const int o0 = (wid & 1) * 32;
    const int nh = (wid >> 1) * 32;

    const uint32_t base = smem_u32(dsm);
    const uint32_t f_row = (uint32_t)((lane & 7) + ((lane >> 3) & 1) * 8);
    const uint32_t kcol = (uint32_t)((lane >> 4) * 8);
    const uint32_t Aa = base + I_A + (f_row * INV_S + kcol) * 2;
    const uint32_t Ba = base + I_B + (f_row * INV_S + kcol) * 2;

    // preload tile-0 coords (indices recomputed inline; only 2 float regs live)
    float p_pre0 = x_out[((size_t)b * NPTS + ch * INV_CHUNK + (tid & 127)) * 2 + ((tid >> 7) & 1)];
    float p_pre1 = x_out[((size_t)b * NPTS + ch * INV_CHUNK + ((tid + 256) & 127)) * 2 + (((tid + 256) >> 7) & 1)];

    float acc[2][4][4];

    for (int t = 0; t < INV_TILES + 1; ++t) {
        __syncthreads();
        // ---- stage basis tile t into buf t&1 (2 chains/thread) ----
        if (t < INV_TILES) {
            char* Bbuf = dsm + I_B + (uint32_t)(t & 1) * I_BUF;
            float pc0 = p_pre0, pc1 = p_pre1;
            if (t + 1 < INV_TILES) {
                const int n1 = ch * INV_CHUNK + (t + 1) * INV_TN;
                p_pre0 = x_out[((size_t)b * NPTS + n1 + (tid & 127)) * 2 + ((tid >> 7) & 1)];
                p_pre1 = x_out[((size_t)b * NPTS + n1 + ((tid + 256) & 127)) * 2 + (((tid + 256) >> 7) & 1)];
            }
            {
                int n   = tid & 127;
                int cbr = (tid >> 7) & 1;
                uint32_t rowb = (uint32_t)(n * (INV_S * 2) + cbr * 128 + 0 * 32);
                stage_chain(pc0, 0, Bbuf + rowb);
            }
            {
                int id  = tid + 256;
                int n   = id & 127;
                int cbr = (id >> 7) & 1;
                uint32_t rowb = (uint32_t)(n * (INV_S * 2) + cbr * 128 + 1 * 32);
                stage_chain(pc1, 1, Bbuf + rowb);
            }
        }
        // ---- MMA tile t-1 from buf (t-1)&1, then store ----
        if (t > 0) {
            const int n0 = ch * INV_CHUNK + (t - 1) * INV_TN;
            const uint32_t roff = (uint32_t)((t - 1) & 1) * I_BUF;
#pragma unroll
            for (int mi = 0; mi < 2; ++mi)
#pragma unroll
                for (int ni = 0; ni < 4; ++ni)
#pragma unroll
                    for (int q = 0; q < 4; ++q) acc[mi][ni][q] = 0.f;
#pragma unroll
            for (int ks = 0; ks < 8; ++ks) {
                const uint32_t co = (uint32_t)(ks * 32);
                uint32_t ah[2][4], bh[2][4];
#pragma unroll
                for (int mi = 0; mi < 2; ++mi)
                    ldsm4(ah[mi], Aa + (uint32_t)((o0 + 16 * mi) * (2 * INV_S)) + co);
#pragma unroll
                for (int g = 0; g < 2; ++g)
                    ldsm4(bh[g], Ba + roff + (uint32_t)((nh + 16 * g) * (2 * INV_S)) + co);
#pragma unroll
                for (int mi = 0; mi < 2; ++mi)
#pragma unroll
                    for (int ni = 0; ni < 4; ++ni)
                        mma_f16(acc[mi][ni], ah[mi], bh[ni >> 1][ni & 1], bh[ni >> 1][(ni & 1) + 2]);
            }
#pragma unroll
            for (int mi = 0; mi < 2; ++mi)
#pragma unroll
                for (int ni = 0; ni < 4; ++ni) {
                    int orow = o0 + 16 * mi + (lane >> 2);
                    int n = n0 + nh + 8 * ni + 2 * (lane & 3);
                    float2 v0 = make_float2(64.f * acc[mi][ni][0], 64.f * acc[mi][ni][1]);
                    float2 v1 = make_float2(64.f * acc[mi][ni][2], 64.f * acc[mi][ni][3]);
                    *reinterpret_cast<float2*>(&out[((size_t)(b * NC + orow)) * NPTS + n])     = v0;
                    *reinterpret_cast<float2*>(&out[((size_t)(b * NC + orow + 8)) * NPTS + n]) = v1;
                }
        }
    }
}

// ---------------------------------------------------------------------------
extern "C" void kernel_launch(void* const* d_in, const int* in_sizes, int n_in,
                              void* d_out, int out_size) {
    const float* x     = (const float*)d_in[0];
    const float* x_in  = (const float*)d_in[1];
    const float* x_out = (const float*)d_in[2];
    const float* w1    = (const float*)d_in[3];
    const float* w2    = (const float*)d_in[4];
    float* out = (float*)d_out;

    cudaFuncSetAttribute(fwd_kernel, cudaFuncAttributeMaxDynamicSharedMemorySize, F_TOT);
    cudaFuncSetAttribute(inv_kernel, cudaFuncAttributeMaxDynamicSharedMemorySize, I_TOT);

    fwd_kernel<<<dim3(NCH, NB), 256, F_TOT>>>(x, x_in);
    mix_kernel<<<dim3(32, NB), 256>>>(w1, w2);
    inv_kernel<<<dim3(NCHI, NB), 256, I_TOT>>>(x_out, out);
}